// round 10
// baseline (speedup 1.0000x reference)
#include <cuda_runtime.h>
#include <cuda_bf16.h>

// text [SEQ=200, BATCH=4096] int32 (row-major text[s*BATCH+b]),
// w [V=50000] f32, bias [1] f32.  out[b] = sum_{unique t in doc b} w[t] + bias.
//
// R10: decouple docs. R9 convoyed 4 docs through 6 block-wide barriers (issue
// 31%, L1 41% -> overlap-limited). Now: one block-wide phase loads text
// coalesced into smem; then each doc is owned by a contiguous 64-thread group
// (2 warps) using its own named barrier (bar.sync g,64). Races use DISJOINT
// per-level tables (A=2048/B=512/C=256 byte slots per doc), one barrier per
// level; every reader reads a slot it wrote in the same phase, so the content
// is always a genuine same-phase racer (no stale-entry hazard). Speculative
// gathers issue right after the remap so L2 latency hides under the cascade.

#define SEQ    200
#define BATCH  4096
#define DOCS   4
#define NTHR   256
#define NITEM  (SEQ * DOCS)       // 800
#define ABITS  11
#define BBITS  9
#define CBITS  8
#define ASZ    (1 << ABITS)       // 2048
#define BSZ    (1 << BBITS)       // 512
#define CSZ    (1 << CBITS)       // 256

__device__ __forceinline__ void bar_grp(int id) {
    asm volatile("bar.sync %0, 64;" :: "r"(id) : "memory");
}

__global__ __launch_bounds__(NTHR, 8)
void MNB_24111946400019_kernel(const int* __restrict__ text,
                               const float* __restrict__ w,
                               const float* __restrict__ bias,
                               float* __restrict__ out)
{
    __shared__ int           toks[DOCS * SEQ];     // 3.2KB
    __shared__ unsigned char tabA[DOCS * ASZ];     // 8KB
    __shared__ unsigned char tabB[DOCS * BSZ];     // 2KB
    __shared__ unsigned char tabC[DOCS * CSZ];     // 1KB
    __shared__ float         part[DOCS][2];

    const int b0  = blockIdx.x * DOCS;
    const int tid = threadIdx.x;

    // ── Block-wide phase: init tables + coalesced text load ──
    {
        int4* a4 = reinterpret_cast<int4*>(tabA);
        int4* b4 = reinterpret_cast<int4*>(tabB);
        int4* c4 = reinterpret_cast<int4*>(tabC);
        const int4 ff = make_int4(-1, -1, -1, -1);
        a4[tid] = ff; a4[tid + NTHR] = ff;                 // 8KB
        if (tid < DOCS * BSZ / 16) b4[tid] = ff;           // 2KB
        if (tid < DOCS * CSZ / 16) c4[tid] = ff;           // 1KB
    }
    #pragma unroll
    for (int k = 0; k < 4; ++k) {
        const int i = tid + k * NTHR;
        if (i < NITEM) {
            const int s = i >> 2, d = i & 3;               // 16B sector / 4 lanes
            toks[d * SEQ + s] = __ldg(&text[s * BATCH + b0 + d]);
        }
    }
    __syncthreads();

    // ── Per-doc groups: g = tid>>6 (2 contiguous warps own doc g) ──
    const int g  = tid >> 6;
    const int l  = tid & 63;
    const int gt = g * SEQ;

    // Re-read own items from smem; fire speculative gathers immediately.
    int   tt[4];
    float wv[4];
    unsigned hh[4];
    #pragma unroll
    for (int k = 0; k < 4; ++k) {
        const int j = l + k * 64;                          // seq idx; k=3 valid iff l<8
        tt[k] = (j < SEQ) ? toks[gt + j] : 0;
    }
    #pragma unroll
    for (int k = 0; k < 4; ++k) wv[k] = __ldg(&w[tt[k]]);  // in flight under races

    // ── Level 1 (table A) ──
    #pragma unroll
    for (int k = 0; k < 4; ++k) {
        const int j = l + k * 64;
        hh[k] = ((unsigned)tt[k] * 2654435761u) >> (32 - ABITS);
        if (j < SEQ) tabA[g * ASZ + hh[k]] = (unsigned char)j;
    }
    bar_grp(g);

    int st[4];                        // 0=drop 1=contribute 2/3=unresolved
    #pragma unroll
    for (int k = 0; k < 4; ++k) {
        st[k] = 0;
        const int j = l + k * 64;
        if (j < SEQ) {
            const int m = tabA[g * ASZ + hh[k]];           // same-phase racer
            if (toks[gt + m] == tt[k]) st[k] = (m == j) ? 1 : 0;
            else                       st[k] = 2;          // ~9.8/doc
        }
    }
    bar_grp(g);                        // readers done before nothing? (A not reused)

    // ── Level 2 (table B, disjoint) ──
    #pragma unroll
    for (int k = 0; k < 4; ++k) {
        hh[k] = ((unsigned)tt[k] * 0x85EBCA77u) >> (32 - BBITS);
        if (st[k] == 2) tabB[g * BSZ + hh[k]] = (unsigned char)(l + k * 64);
    }
    bar_grp(g);
    #pragma unroll
    for (int k = 0; k < 4; ++k) {
        if (st[k] == 2) {
            const int m = tabB[g * BSZ + hh[k]];
            if (toks[gt + m] == tt[k]) st[k] = (m == (l + k * 64)) ? 1 : 0;
            else                       st[k] = 3;          // ~0.09/doc
        }
    }

    // ── Level 3 (table C, disjoint) ──
    #pragma unroll
    for (int k = 0; k < 4; ++k) {
        hh[k] = ((unsigned)tt[k] * 0xC2B2AE3Du) >> (32 - CBITS);
        if (st[k] == 3) tabC[g * CSZ + hh[k]] = (unsigned char)(l + k * 64);
    }
    bar_grp(g);

    float v = 0.0f;
    #pragma unroll
    for (int k = 0; k < 4; ++k) {
        const int j = l + k * 64;
        int c = st[k];
        if (c == 3) {
            const int m = tabC[g * CSZ + hh[k]];
            if (toks[gt + m] == tt[k]) {
                c = (m == j) ? 1 : 0;
            } else {
                // Level 4 (~1e-5/doc): exact first-occurrence scan.
                int f = 0;
                while (toks[gt + f] != tt[k]) ++f;
                c = (f == j) ? 1 : 0;
            }
        }
        if (c == 1) v += wv[k];
    }

    // ── Per-doc reduction: each warp is entirely in one doc ──
    v += __shfl_xor_sync(0xffffffffu, v, 16);
    v += __shfl_xor_sync(0xffffffffu, v, 8);
    v += __shfl_xor_sync(0xffffffffu, v, 4);
    v += __shfl_xor_sync(0xffffffffu, v, 2);
    v += __shfl_xor_sync(0xffffffffu, v, 1);
    if ((tid & 31) == 0) part[g][(tid >> 5) & 1] = v;
    bar_grp(g);

    if (l == 0) out[b0 + g] = part[g][0] + part[g][1] + bias[0];
}

extern "C" void kernel_launch(void* const* d_in, const int* in_sizes, int n_in,
                              void* d_out, int out_size)
{
    const int*   text = (const int*)d_in[0];
    const float* w    = (const float*)d_in[1];
    const float* bias = (const float*)d_in[2];
    float*       out  = (float*)d_out;

    MNB_24111946400019_kernel<<<BATCH / DOCS, NTHR>>>(text, w, bias, out);
}

// round 11
// speedup vs baseline: 1.0058x; 1.0058x over previous
#include <cuda_runtime.h>
#include <cuda_bf16.h>

// text [SEQ=200, BATCH=4096] int32 (row-major text[s*BATCH+b]),
// w [V=50000] f32, bias [1] f32.  out[b] = sum_{unique t in doc b} w[t] + bias.
//
// R11: R9 shape (named barriers in R10 capped occupancy at 42% — reverted).
// Levels 2/3/4 of the race cascade are replaced by an EXACT per-doc atomicCAS
// insert table for the ~10 unresolved items/doc: same-token threads share
// resolution state after level 1, so first-CAS-wins gives exactly-once with
// ~40 cheap spread ATOMS per block and ZERO extra barriers. 256 int slots/doc
// >= 200 tokens -> table can never fill -> probing provably terminates.
// Barriers: 6 -> 3.

#define SEQ    200
#define BATCH  4096
#define DOCS   4
#define NTHR   256
#define NITEM  (SEQ * DOCS)       // 800
#define HBITS  11
#define HSIZE  (1 << HBITS)       // 2048 byte slots per doc
#define CTSZ   256                // exact CAS table slots per doc (>= SEQ)

__global__ __launch_bounds__(NTHR, 8)
void MNB_24111946400019_kernel(const int* __restrict__ text,
                               const float* __restrict__ w,
                               const float* __restrict__ bias,
                               float* __restrict__ out)
{
    __shared__ int           toks[DOCS * SEQ];          // 3.2KB
    __shared__ unsigned char marker[DOCS * HSIZE];      // 8KB
    __shared__ int           ctab[DOCS * CTSZ];         // 4KB exact fallback
    __shared__ float         part[DOCS][9];

    const int b0  = blockIdx.x * DOCS;
    const int tid = threadIdx.x;
    const int d   = tid & 3;                 // this thread's doc (256%4==0)
    const int dt  = d * SEQ;
    const int dm  = d * HSIZE;

    // Coalesced text load (item i=s*4+d) + speculative weight gathers: the
    // ~250cyc L2 latency hides under init + the level-1 race.
    int   tt[4];
    float wv[4];
    #pragma unroll
    for (int k = 0; k < 4; ++k) {
        const int i = tid + k * NTHR;
        const int s = i >> 2;
        tt[k] = (i < NITEM) ? __ldg(&text[s * BATCH + b0 + d]) : 0;
    }
    #pragma unroll
    for (int k = 0; k < 4; ++k) wv[k] = __ldg(&w[tt[k]]);     // in flight

    // Init marker (0xFF) and CAS table (-1).
    {
        int4* m4 = reinterpret_cast<int4*>(marker);
        const int4 ff = make_int4(-1, -1, -1, -1);
        m4[tid]        = ff;
        m4[tid + NTHR] = ff;
        reinterpret_cast<int4*>(ctab)[tid] = ff;               // 4KB
    }
    #pragma unroll
    for (int k = 0; k < 4; ++k) {
        const int i = tid + k * NTHR;
        if (i < NITEM) toks[dt + (i >> 2)] = tt[k];
    }
    __syncthreads();

    // ── Level 1: racing byte store ──
    unsigned hh[4];
    #pragma unroll
    for (int k = 0; k < 4; ++k) {
        const int i = tid + k * NTHR;
        hh[k] = ((unsigned)tt[k] * 2654435761u) >> (32 - HBITS);
        if (i < NITEM) marker[dm + hh[k]] = (unsigned char)(i >> 2);
    }
    __syncthreads();

    // Read winners; unresolved go straight to the exact CAS table (no barrier:
    // ctab was initialized before the first sync, and same-token threads all
    // take the same branch here, so exactly-once holds).
    float v = 0.0f;
    #pragma unroll
    for (int k = 0; k < 4; ++k) {
        const int i = tid + k * NTHR;
        if (i < NITEM) {
            const int s = i >> 2;
            const int m = marker[dm + hh[k]];      // genuine same-phase racer
            bool contrib;
            if (toks[dt + m] == tt[k]) {
                contrib = (m == s);                // winner / duplicate-drop
            } else {
                // ~10/doc: exact first-insert via CAS (spread ATOMS, cheap).
                unsigned h = ((unsigned)tt[k] * 0x9E3779B1u) >> (32 - 8);
                contrib = false;
                for (;;) {
                    const int old = atomicCAS(&ctab[d * CTSZ + h], -1, tt[k]);
                    if (old == -1) { contrib = true;  break; }   // first insert
                    if (old == tt[k]) {               break; }   // dup of insert
                    h = (h + 1) & (CTSZ - 1);         // probe; table never full
                }
            }
            if (contrib) v += wv[k];
        }
    }

    // ── Per-doc reduction: lanes with equal (lane&3) share a doc ──
    v += __shfl_xor_sync(0xffffffffu, v, 16);
    v += __shfl_xor_sync(0xffffffffu, v, 8);
    v += __shfl_xor_sync(0xffffffffu, v, 4);
    if ((tid & 31) < 4) part[d][tid >> 5] = v;           // 8 warps
    __syncthreads();

    if (tid < 32) {
        const int dd = tid >> 3;                         // doc 0..3
        const int j  = tid & 7;                          // warp slot
        float s = part[dd][j];
        s += __shfl_xor_sync(0xffffffffu, s, 4);
        s += __shfl_xor_sync(0xffffffffu, s, 2);
        s += __shfl_xor_sync(0xffffffffu, s, 1);
        if (j == 0) out[b0 + dd] = s + bias[0];
    }
}

extern "C" void kernel_launch(void* const* d_in, const int* in_sizes, int n_in,
                              void* d_out, int out_size)
{
    const int*   text = (const int*)d_in[0];
    const float* w    = (const float*)d_in[1];
    const float* bias = (const float*)d_in[2];
    float*       out  = (float*)d_out;

    MNB_24111946400019_kernel<<<BATCH / DOCS, NTHR>>>(text, w, bias, out);
}